// round 1
// baseline (speedup 1.0000x reference)
#include <cuda_runtime.h>
#include <cuda_bf16.h>
#include <cstdint>

// HMM forward: T=1024, S=512, D=32, K=64
// Phase 1: emission probs (max-normalized per (t,s)) via packed f32x2 FMA
// Phase 2: per-sequence forward recursion, warp-per-sequence, A in registers,
//          stale-scale normalization (exactly compensated in log domain)

#define HT 1024
#define HS 512
#define HD 32
#define HK 64
#define LOG2PI_F 1.8378770664093453f

// -------- device scratch (no cudaMalloc allowed) --------
__device__ float  g_P[(size_t)HT * HS * HK];   // 128 MB scaled emission probs
__device__ float  g_M[(size_t)HT * HS];        // per-(t,s) log-max (natural log)
__device__ float4 g_W4[16 * HK];               // [group g][k]: (inv_2g, inv_2g+1, -2mu*inv_2g, -2mu*inv_2g+1)
__device__ float  g_C[HK];                     // c_k = sum mu^2*inv + sum log cov + D*log(2pi)
__device__ float  g_loglik[HS];

// -------- packed f32x2 helpers --------
__device__ __forceinline__ void fma2(unsigned long long& d, unsigned long long a,
                                     unsigned long long b, unsigned long long c) {
    asm("fma.rn.f32x2 %0, %1, %2, %3;" : "=l"(d) : "l"(a), "l"(b), "l"(c));
}
__device__ __forceinline__ unsigned long long pk2(float lo, float hi) {
    unsigned long long r;
    asm("mov.b64 %0, {%1, %2};" : "=l"(r) : "f"(lo), "f"(hi));
    return r;
}
__device__ __forceinline__ void unpk2(float& lo, float& hi, unsigned long long v) {
    asm("mov.b64 {%0, %1}, %2;" : "=f"(lo), "=f"(hi) : "l"(v));
}

// -------- prep: build per-state coefficients --------
__global__ void hmm_prep(const float* __restrict__ means, const float* __restrict__ covars) {
    int k = threadIdx.x;
    if (k >= HK) return;
    float c = (float)HD * LOG2PI_F;
    #pragma unroll
    for (int g = 0; g < 16; ++g) {
        int d0 = 2 * g, d1 = 2 * g + 1;
        float cv0 = covars[k * HD + d0], cv1 = covars[k * HD + d1];
        float mu0 = means [k * HD + d0], mu1 = means [k * HD + d1];
        float iv0 = 1.0f / cv0, iv1 = 1.0f / cv1;
        c += mu0 * mu0 * iv0 + __logf(cv0);
        c += mu1 * mu1 * iv1 + __logf(cv1);
        float4 v;
        v.x = iv0; v.y = iv1;
        v.z = -2.0f * mu0 * iv0; v.w = -2.0f * mu1 * iv1;
        g_W4[g * HK + k] = v;
    }
    g_C[k] = c;
}

// -------- emission: warp computes one (t,s) row at a time; lane -> states {lane, lane+32} --------
#define EM_CTAS 2048
#define EM_THREADS 256
#define EM_TASKS_PER_WARP 32

__global__ void __launch_bounds__(EM_THREADS, 1) hmm_emission(const float* __restrict__ data) {
    __shared__ float sx[8][2][HD];   // per-warp double-buffered x row
    int lane = threadIdx.x & 31;
    int wid  = threadIdx.x >> 5;
    int gw   = blockIdx.x * (EM_THREADS / 32) + wid;
    int ts0  = gw * EM_TASKS_PER_WARP;

    // per-lane coefficient registers (2 states: kA=lane, kB=lane+32)
    unsigned long long w1A[16], w2A[16], w1B[16], w2B[16];
    #pragma unroll
    for (int g = 0; g < 16; ++g) {
        float4 a = g_W4[g * HK + lane];
        float4 b = g_W4[g * HK + lane + 32];
        w1A[g] = pk2(a.x, a.y); w2A[g] = pk2(a.z, a.w);
        w1B[g] = pk2(b.x, b.y); w2B[g] = pk2(b.z, b.w);
    }
    float cA = g_C[lane], cB = g_C[lane + 32];

    float xl = __ldg(&data[(size_t)ts0 * HD + lane]);
    for (int i = 0; i < EM_TASKS_PER_WARP; ++i) {
        int ts = ts0 + i;
        sx[wid][i & 1][lane] = xl;
        if (i + 1 < EM_TASKS_PER_WARP)
            xl = __ldg(&data[(size_t)(ts + 1) * HD + lane]);
        __syncwarp();
        const unsigned long long* xb =
            reinterpret_cast<const unsigned long long*>(sx[wid][i & 1]);
        unsigned long long accA = 0ULL, accB = 0ULL;
        #pragma unroll
        for (int g = 0; g < 16; ++g) {
            unsigned long long x2 = xb[g];
            unsigned long long tA, tB;
            fma2(tA, x2, w1A[g], w2A[g]);
            fma2(accA, x2, tA, accA);
            fma2(tB, x2, w1B[g], w2B[g]);
            fma2(accB, x2, tB, accB);
        }
        float qa0, qa1, qb0, qb1;
        unpk2(qa0, qa1, accA);
        unpk2(qb0, qb1, accB);
        float la = -0.5f * ((qa0 + qa1) + cA);
        float lb = -0.5f * ((qb0 + qb1) + cB);
        float mm = fmaxf(la, lb);
        #pragma unroll
        for (int off = 16; off; off >>= 1)
            mm = fmaxf(mm, __shfl_xor_sync(0xffffffffu, mm, off));
        float pa = __expf(la - mm);
        float pb = __expf(lb - mm);
        size_t base = (size_t)ts * HK;
        g_P[base + lane]      = pa;
        g_P[base + 32 + lane] = pb;
        if (lane == 0) g_M[ts] = mm;
        __syncwarp();
    }
}

// -------- recursion: warp-per-sequence, A in registers, stale-scale normalization --------
__global__ void __launch_bounds__(128, 1) hmm_recursion(const float* __restrict__ Atr,
                                                        const float* __restrict__ initp,
                                                        float* __restrict__ alpha_out,
                                                        int write_alpha) {
    __shared__ float sv[4][2][HK];
    int lane = threadIdx.x & 31;
    int w    = threadIdx.x >> 5;
    int s    = blockIdx.x * 4 + w;

    // transition matrix columns (lane, lane+32) in registers
    float Areg[64], Breg[64];
    #pragma unroll
    for (int i = 0; i < 64; ++i) {
        Areg[i] = __ldg(&Atr[i * HK + lane]);
        Breg[i] = __ldg(&Atr[i * HK + 32 + lane]);
    }

    const size_t sbase = (size_t)s * HK;
    const size_t tstr  = (size_t)HS * HK;   // 32768

    // t = 0
    float w0 = __ldg(&initp[lane])      * __ldg(&g_P[sbase + lane]);
    float w1 = __ldg(&initp[lane + 32]) * __ldg(&g_P[sbase + 32 + lane]);
    float L = __ldg(&g_M[s]);
    sv[w][0][lane] = w0;
    sv[w][0][lane + 32] = w1;
    __syncwarp();
    float dsum = w0 + w1;
    #pragma unroll
    for (int off = 16; off; off >>= 1)
        dsum += __shfl_xor_sync(0xffffffffu, dsum, off);
    float r = 1.0f / dsum;
    float lnd = __logf(dsum);

    // prefetch t=1, t=2
    float pc0 = __ldg(&g_P[tstr * 1 + sbase + lane]);
    float pc1 = __ldg(&g_P[tstr * 1 + sbase + 32 + lane]);
    float mc  = __ldg(&g_M[1 * HS + s]);
    float pn0 = __ldg(&g_P[tstr * 2 + sbase + lane]);
    float pn1 = __ldg(&g_P[tstr * 2 + sbase + 32 + lane]);
    float mn  = __ldg(&g_M[2 * HS + s]);

    for (int t = 1; t < HT; ++t) {
        int tf = (t + 2 < HT) ? (t + 2) : (HT - 1);
        float pf0 = __ldg(&g_P[tstr * (size_t)tf + sbase + lane]);
        float pf1 = __ldg(&g_P[tstr * (size_t)tf + sbase + 32 + lane]);
        float mf  = __ldg(&g_M[(size_t)tf * HS + s]);

        const float* rb = sv[w][(t - 1) & 1];
        float a0 = 0.0f, a1 = 0.0f;
        #pragma unroll
        for (int i = 0; i < 64; ++i) {
            float vi = rb[i];
            a0 = fmaf(vi, Areg[i], a0);
            a1 = fmaf(vi, Breg[i], a1);
        }
        float u0 = pc0 * a0;
        float u1 = pc1 * a1;
        w0 = u0 * r;            // stale scale: r = 1/d_{t-1}
        w1 = u1 * r;
        float* wb = sv[w][t & 1];
        wb[lane] = w0;
        wb[lane + 32] = w1;
        L += mc + lnd;          // exact compensation: + ln d_{t-1}
        __syncwarp();

        // off-critical-path: reduce d_t (overlaps next step's matvec)
        dsum = w0 + w1;
        #pragma unroll
        for (int off = 16; off; off >>= 1)
            dsum += __shfl_xor_sync(0xffffffffu, dsum, off);
        r = 1.0f / dsum;
        lnd = __logf(dsum);

        pc0 = pn0; pc1 = pn1; mc = mn;
        pn0 = pf0; pn1 = pf1; mn = mf;
    }

    // final: alpha = w / sum(w); loglik_s = L + ln(sum(w_T))
    if (write_alpha) {
        alpha_out[s * HK + lane]      = w0 * r;
        alpha_out[s * HK + 32 + lane] = w1 * r;
    }
    if (lane == 0) g_loglik[s] = L + lnd;
}

// -------- finalize: deterministic tree-sum of per-sequence logliks --------
__global__ void hmm_finalize(float* __restrict__ scal) {
    __shared__ float red[HS];
    int tid = threadIdx.x;
    red[tid] = g_loglik[tid];
    __syncthreads();
    for (int st = HS / 2; st > 0; st >>= 1) {
        if (tid < st) red[tid] += red[tid + st];
        __syncthreads();
    }
    if (tid == 0) scal[0] = -red[0];
}

extern "C" void kernel_launch(void* const* d_in, const int* in_sizes, int n_in,
                              void* d_out, int out_size) {
    const float* data   = (const float*)d_in[0];
    const float* initp  = (const float*)d_in[1];
    const float* trans  = (const float*)d_in[2];
    const float* means  = (const float*)d_in[3];
    const float* covars = (const float*)d_in[4];
    float* out = (float*)d_out;

    hmm_prep<<<1, 64>>>(means, covars);
    hmm_emission<<<EM_CTAS, EM_THREADS>>>(data);

    const int AK = HS * HK;  // 32768
    int write_alpha = (out_size >= AK) ? 1 : 0;
    float* scal = nullptr;
    if (out_size == 1)       scal = out;
    else if (out_size > AK)  scal = out + AK;

    hmm_recursion<<<HS / 4, 128>>>(trans, initp, write_alpha ? out : out, write_alpha);
    if (scal) hmm_finalize<<<1, HS>>>(scal);
}

// round 2
// speedup vs baseline: 1.2696x; 1.2696x over previous
#include <cuda_runtime.h>
#include <cuda_bf16.h>
#include <cstdint>

// HMM forward: T=1024, S=512, D=32, K=64
// Emission: raw p = exp2(scaled quad) via packed f32x2 FMA, no per-row normalization
//           (matches reference's raw fp32 exp regime). States paired (2l, 2l+1).
// Recursion: warp-per-sequence, A packed as f32x2 input-pairs in registers,
//            deferred stale-scale (r folded into next step's p multiply, exact
//            telescoping compensation in log2 domain).

#define HT 1024
#define HS 512
#define HD 32
#define HK 64
#define LOG2PI_F 1.8378770664093453f
#define NEG_HALF_LOG2E -0.72134752044448169f
#define LN2_F 0.69314718055994531f

typedef unsigned long long ull;

// -------- device scratch (no cudaMalloc allowed) --------
__device__ float  g_P[(size_t)HT * HS * HK];   // 128 MB raw emission probs
__device__ float4 g_W4[16 * HK];               // [g][k]: sc*(inv0, inv1, -2mu0*inv0, -2mu1*inv1)
__device__ float  g_C[HK];                     // sc*(sum mu^2 inv + sum log cov + D log2pi)
__device__ float  g_loglik[HS];                // per-seq log2-likelihood

// -------- packed f32x2 helpers --------
__device__ __forceinline__ void fma2(ull& d, ull a, ull b, ull c) {
    asm("fma.rn.f32x2 %0, %1, %2, %3;" : "=l"(d) : "l"(a), "l"(b), "l"(c));
}
__device__ __forceinline__ void add2(ull& d, ull a, ull b) {
    asm("add.rn.f32x2 %0, %1, %2;" : "=l"(d) : "l"(a), "l"(b));
}
__device__ __forceinline__ void mul2(ull& d, ull a, ull b) {
    asm("mul.rn.f32x2 %0, %1, %2;" : "=l"(d) : "l"(a), "l"(b));
}
__device__ __forceinline__ ull pk2(float lo, float hi) {
    ull r;
    asm("mov.b64 %0, {%1, %2};" : "=l"(r) : "f"(lo), "f"(hi));
    return r;
}
__device__ __forceinline__ void unpk2(float& lo, float& hi, ull v) {
    asm("mov.b64 {%0, %1}, %2;" : "=f"(lo), "=f"(hi) : "l"(v));
}
__device__ __forceinline__ float ex2a(float x) {
    float r; asm("ex2.approx.f32 %0, %1;" : "=f"(r) : "f"(x)); return r;
}
__device__ __forceinline__ float lg2a(float x) {
    float r; asm("lg2.approx.f32 %0, %1;" : "=f"(r) : "f"(x)); return r;
}
__device__ __forceinline__ float rcpa(float x) {
    float r; asm("rcp.approx.f32 %0, %1;" : "=f"(r) : "f"(x)); return r;
}

// -------- prep: per-state coefficients prescaled by -log2(e)/2 --------
__global__ void hmm_prep(const float* __restrict__ means, const float* __restrict__ covars) {
    int k = threadIdx.x;
    if (k >= HK) return;
    float c = (float)HD * LOG2PI_F;
    #pragma unroll
    for (int g = 0; g < 16; ++g) {
        int d0 = 2 * g, d1 = 2 * g + 1;
        float cv0 = covars[k * HD + d0], cv1 = covars[k * HD + d1];
        float mu0 = means [k * HD + d0], mu1 = means [k * HD + d1];
        float iv0 = 1.0f / cv0, iv1 = 1.0f / cv1;
        c += mu0 * mu0 * iv0 + logf(cv0);
        c += mu1 * mu1 * iv1 + logf(cv1);
        float4 v;
        v.x = NEG_HALF_LOG2E * iv0;
        v.y = NEG_HALF_LOG2E * iv1;
        v.z = NEG_HALF_LOG2E * (-2.0f * mu0 * iv0);
        v.w = NEG_HALF_LOG2E * (-2.0f * mu1 * iv1);
        g_W4[g * HK + k] = v;
    }
    g_C[k] = NEG_HALF_LOG2E * c;
}

// -------- emission: warp per (t,s) row; lane -> states (2l, 2l+1) --------
#define EM_CTAS 4096
#define EM_THREADS 128
#define EM_TPW 32

__global__ void __launch_bounds__(EM_THREADS, 3) hmm_emission(const float* __restrict__ data) {
    __shared__ __align__(16) float sx[4][2][HD];
    int lane = threadIdx.x & 31;
    int wid  = threadIdx.x >> 5;
    int gw   = blockIdx.x * (EM_THREADS / 32) + wid;
    int ts0  = gw * EM_TPW;

    int kA = 2 * lane, kB = 2 * lane + 1;
    ull w1A[16], w2A[16], w1B[16], w2B[16];
    #pragma unroll
    for (int g = 0; g < 16; ++g) {
        float4 a = g_W4[g * HK + kA];
        float4 b = g_W4[g * HK + kB];
        w1A[g] = pk2(a.x, a.y); w2A[g] = pk2(a.z, a.w);
        w1B[g] = pk2(b.x, b.y); w2B[g] = pk2(b.z, b.w);
    }
    float cA = g_C[kA], cB = g_C[kB];

    // depth-4 x prefetch ring
    float xr[4];
    #pragma unroll
    for (int j = 0; j < 4; ++j)
        xr[j] = __ldg(&data[(size_t)(ts0 + j) * HD + lane]);

    ull* Pout = reinterpret_cast<ull*>(g_P);

    for (int i = 0; i < EM_TPW; ++i) {
        int ts = ts0 + i;
        sx[wid][i & 1][lane] = xr[i & 3];
        if (i + 4 < EM_TPW)
            xr[i & 3] = __ldg(&data[(size_t)(ts + 4) * HD + lane]);
        __syncwarp();
        const ull* xb = reinterpret_cast<const ull*>(sx[wid][i & 1]);
        ull aA0 = 0ULL, aA1 = 0ULL, aB0 = 0ULL, aB1 = 0ULL;
        #pragma unroll
        for (int g = 0; g < 8; ++g) {
            ull x2 = xb[g];
            ull tA, tB;
            fma2(tA, x2, w1A[g], w2A[g]);
            fma2(aA0, x2, tA, aA0);
            fma2(tB, x2, w1B[g], w2B[g]);
            fma2(aB0, x2, tB, aB0);
        }
        #pragma unroll
        for (int g = 8; g < 16; ++g) {
            ull x2 = xb[g];
            ull tA, tB;
            fma2(tA, x2, w1A[g], w2A[g]);
            fma2(aA1, x2, tA, aA1);
            fma2(tB, x2, w1B[g], w2B[g]);
            fma2(aB1, x2, tB, aB1);
        }
        ull sA, sB;
        add2(sA, aA0, aA1);
        add2(sB, aB0, aB1);
        float qa0, qa1, qb0, qb1;
        unpk2(qa0, qa1, sA);
        unpk2(qb0, qb1, sB);
        float pa = ex2a((qa0 + qa1) + cA);   // = exp(-0.5*(quad+c))
        float pb = ex2a((qb0 + qb1) + cB);
        Pout[(size_t)ts * 32 + lane] = pk2(pa, pb);
        __syncwarp();
    }
}

// -------- recursion: warp-per-sequence; lane -> output states (2l, 2l+1) --------
__global__ void __launch_bounds__(128, 1) hmm_recursion(const float* __restrict__ trans,
                                                        const float* __restrict__ initp,
                                                        float* __restrict__ alpha_out,
                                                        int write_alpha) {
    __shared__ __align__(16) float sv[4][2][HK];
    int lane = threadIdx.x & 31;
    int w    = threadIdx.x >> 5;
    int s    = blockIdx.x * 4 + w;
    int k0 = 2 * lane, k1 = 2 * lane + 1;

    // A packed over input pairs, per output column
    ull Ap0[32], Ap1[32];
    #pragma unroll
    for (int j = 0; j < 32; ++j) {
        Ap0[j] = pk2(__ldg(&trans[(2 * j) * HK + k0]), __ldg(&trans[(2 * j + 1) * HK + k0]));
        Ap1[j] = pk2(__ldg(&trans[(2 * j) * HK + k1]), __ldg(&trans[(2 * j + 1) * HK + k1]));
    }

    const ull* Pin = reinterpret_cast<const ull*>(g_P);
    const int sb = s * 32;          // ull offset of this sequence within a t-slab
    const int tstr = HS * 32;       // ull stride per t (16384)

    // t = 0
    ull p0 = __ldg(&Pin[sb + lane]);
    float p0l, p0h;
    unpk2(p0l, p0h, p0);
    float w0 = __ldg(&initp[k0]) * p0l;
    float w1 = __ldg(&initp[k1]) * p0h;
    ull u2 = pk2(w0, w1);
    reinterpret_cast<ull*>(sv[w][0])[lane] = u2;
    __syncwarp();
    float dsum = w0 + w1;
    #pragma unroll
    for (int off = 16; off; off >>= 1)
        dsum += __shfl_xor_sync(0xffffffffu, dsum, off);
    float r   = rcpa(dsum);
    float lnd = lg2a(dsum);
    float L = 0.0f;

    // depth-4 p prefetch ring (t = 1..4)
    ull pp[4];
    #pragma unroll
    for (int j = 0; j < 4; ++j)
        pp[j] = __ldg(&Pin[(size_t)(j + 1) * tstr + sb + lane]);

    // pr for step 1: p_1 * r_0 (scale deferred into p-multiply)
    ull rr = pk2(r, r);
    ull pr;
    mul2(pr, pp[0], rr);

    for (int t = 1; t < HT; ++t) {
        // prefetch p for t+4
        if (t + 4 < HT)
            pp[(t - 1) & 3] = __ldg(&Pin[(size_t)(t + 4) * tstr + sb + lane]);

        const ull* vb = reinterpret_cast<const ull*>(sv[w][(t - 1) & 1]);
        ull a00 = 0ULL, a01 = 0ULL, a10 = 0ULL, a11 = 0ULL;
        #pragma unroll
        for (int j = 0; j < 16; ++j) {
            ull v = vb[j];
            fma2(a00, v, Ap0[j], a00);
            fma2(a10, v, Ap1[j], a10);
        }
        #pragma unroll
        for (int j = 16; j < 32; ++j) {
            ull v = vb[j];
            fma2(a01, v, Ap0[j], a01);
            fma2(a11, v, Ap1[j], a11);
        }
        ull s0, s1;
        add2(s0, a00, a01);
        add2(s1, a10, a11);
        float s0l, s0h, s1l, s1h;
        unpk2(s0l, s0h, s0);
        unpk2(s1l, s1h, s1);
        ull apk = pk2(s0l + s0h, s1l + s1h);
        mul2(u2, apk, pr);                       // u_t = p_t * r_{t-1} * (u_{t-1} @ A)
        reinterpret_cast<ull*>(sv[w][t & 1])[lane] = u2;
        L += lnd;                                // log2 d_{t-1}
        __syncwarp();

        // reduction (overlaps next step's matvec)
        unpk2(w0, w1, u2);
        dsum = w0 + w1;
        #pragma unroll
        for (int off = 16; off; off >>= 1)
            dsum += __shfl_xor_sync(0xffffffffu, dsum, off);
        r   = rcpa(dsum);
        lnd = lg2a(dsum);
        rr = pk2(r, r);
        mul2(pr, pp[t & 3], rr);                 // pr for step t+1
    }

    if (write_alpha) {
        ull an;
        mul2(an, u2, rr);
        reinterpret_cast<ull*>(alpha_out)[sb + lane] = an;
    }
    if (lane == 0) g_loglik[s] = L + lnd;        // sum_t log2 d_t
}

// -------- finalize: deterministic tree-sum, convert log2 -> ln, negate --------
__global__ void hmm_finalize(float* __restrict__ scal) {
    __shared__ float red[HS];
    int tid = threadIdx.x;
    red[tid] = g_loglik[tid];
    __syncthreads();
    for (int st = HS / 2; st > 0; st >>= 1) {
        if (tid < st) red[tid] += red[tid + st];
        __syncthreads();
    }
    if (tid == 0) scal[0] = -red[0] * LN2_F;
}

extern "C" void kernel_launch(void* const* d_in, const int* in_sizes, int n_in,
                              void* d_out, int out_size) {
    const float* data   = (const float*)d_in[0];
    const float* initp  = (const float*)d_in[1];
    const float* trans  = (const float*)d_in[2];
    const float* means  = (const float*)d_in[3];
    const float* covars = (const float*)d_in[4];
    float* out = (float*)d_out;

    hmm_prep<<<1, 64>>>(means, covars);
    hmm_emission<<<EM_CTAS, EM_THREADS>>>(data);

    const int AK = HS * HK;  // 32768
    int write_alpha = (out_size >= AK) ? 1 : 0;
    float* scal = nullptr;
    if (out_size == 1)       scal = out;
    else if (out_size > AK)  scal = out + AK;

    hmm_recursion<<<HS / 4, 128>>>(trans, initp, out, write_alpha);
    if (scal) hmm_finalize<<<1, HS>>>(scal);
}